// round 1
// baseline (speedup 1.0000x reference)
#include <cuda_runtime.h>
#include <cuda_bf16.h>
#include <math.h>

// Problem constants
#define B_SZ 2
#define T_SZ 2048
#define C_SZ 2048
#define NH 32
#define NKV 8
#define HD 64
#define ROWS (B_SZ * T_SZ)          // 4096
#define KVDIM (NKV * HD)            // 512

// Scratch (allocation-free: __device__ globals)
__device__ float g_q[ROWS * C_SZ];
__device__ float g_k[ROWS * KVDIM];
__device__ float g_v[ROWS * KVDIM];
__device__ float g_y[ROWS * C_SZ];

// ---------------------------------------------------------------------------
// Tiled fp32 GEMM: C[M,N] = A[M,K] @ B[K,N].  M,N multiples of 64, K of 16.
// ---------------------------------------------------------------------------
#define GBM 64
#define GBN 64
#define GBK 16

__global__ __launch_bounds__(256) void gemm_kernel(const float* __restrict__ A,
                                                   const float* __restrict__ B,
                                                   float* __restrict__ C,
                                                   int M, int N, int K) {
    __shared__ float As[GBK][GBM + 4];   // transposed A tile, padded
    __shared__ float Bs[GBK][GBN];

    int tid = threadIdx.x;
    int tx = tid & 15;          // 0..15
    int ty = tid >> 4;          // 0..15
    int brow = blockIdx.y * GBM;
    int bcol = blockIdx.x * GBN;

    // load mapping
    int arow  = tid >> 2;            // 0..63
    int acol4 = (tid & 3) * 4;       // 0,4,8,12
    int brow_l = tid >> 4;           // 0..15
    int bcol4  = (tid & 15) * 4;     // 0..60

    float acc[4][4] = {};

    for (int k0 = 0; k0 < K; k0 += GBK) {
        float4 a4 = *(const float4*)&A[(size_t)(brow + arow) * K + k0 + acol4];
        As[acol4 + 0][arow] = a4.x;
        As[acol4 + 1][arow] = a4.y;
        As[acol4 + 2][arow] = a4.z;
        As[acol4 + 3][arow] = a4.w;
        *(float4*)&Bs[brow_l][bcol4] =
            *(const float4*)&B[(size_t)(k0 + brow_l) * N + bcol + bcol4];
        __syncthreads();

#pragma unroll
        for (int kk = 0; kk < GBK; kk++) {
            float4 av = *(float4*)&As[kk][ty * 4];
            float4 bv = *(float4*)&Bs[kk][tx * 4];
            float a[4] = {av.x, av.y, av.z, av.w};
            float b[4] = {bv.x, bv.y, bv.z, bv.w};
#pragma unroll
            for (int i = 0; i < 4; i++)
#pragma unroll
                for (int j = 0; j < 4; j++)
                    acc[i][j] += a[i] * b[j];
        }
        __syncthreads();
    }

#pragma unroll
    for (int i = 0; i < 4; i++) {
        float4 o = make_float4(acc[i][0], acc[i][1], acc[i][2], acc[i][3]);
        *(float4*)&C[(size_t)(brow + ty * 4 + i) * N + bcol + tx * 4] = o;
    }
}

// ---------------------------------------------------------------------------
// RoPE in-place on [ROWS, nheads*64] (row = b*T + t). Pair i in [0,32).
// out[i]    = x[i]*cos - x[i+32]*sin
// out[i+32] = x[i+32]*cos + x[i]*sin ;  angle = t * 10000^(-i/32)
// ---------------------------------------------------------------------------
__global__ void rope_kernel(float* __restrict__ x, int nheads) {
    int idx = blockIdx.x * blockDim.x + threadIdx.x;
    int total = ROWS * nheads * 32;
    if (idx >= total) return;
    int i = idx & 31;
    int h = (idx >> 5) % nheads;
    int row = idx / (32 * nheads);
    int t = row & (T_SZ - 1);

    // ln(10000)/32
    float invf = expf(-(float)i * 0.28782313662425574f);
    float ang = (float)t * invf;
    float c = cosf(ang), s = sinf(ang);

    float* p = x + (size_t)row * (nheads * HD) + h * HD;
    float x0 = p[i];
    float x1 = p[i + 32];
    p[i]      = x0 * c - x1 * s;
    p[i + 32] = x1 * c + x0 * s;
}

// ---------------------------------------------------------------------------
// Flash attention (causal, fp32). Block = 64 query rows x one head x one batch.
// 256 threads: row = tid/4 (0..63), quad = tid%4.
//   S stage: thread owns 16 cols j = quad + 4*jj
//   PV stage: thread owns 16 dims d = quad*16 + dd
// smem: Qs,Ks,Vs,Ps each [64][68] floats (dynamic, 69632 B)
// ---------------------------------------------------------------------------
#define FPAD 68
__global__ __launch_bounds__(256) void flash_kernel(const float* __restrict__ q,
                                                    const float* __restrict__ k,
                                                    const float* __restrict__ v,
                                                    float* __restrict__ y) {
    extern __shared__ float sm[];
    float (*Qs)[FPAD] = (float(*)[FPAD])sm;
    float (*Ks)[FPAD] = (float(*)[FPAD])(sm + 64 * FPAD);
    float (*Vs)[FPAD] = (float(*)[FPAD])(sm + 2 * 64 * FPAD);
    float (*Ps)[FPAD] = (float(*)[FPAD])(sm + 3 * 64 * FPAD);

    int qt = blockIdx.x;     // query tile 0..31
    int h  = blockIdx.y;     // head 0..31
    int b  = blockIdx.z;     // batch
    int hk = h >> 2;         // kv head

    int tid = threadIdx.x;
    int r = tid >> 2;        // 0..63
    int quad = tid & 3;

    // load Q tile, scaled by 1/sqrt(64)
    {
        int c4 = (tid & 15) * 4;
        int row0 = tid >> 4;   // 0..15
#pragma unroll
        for (int p = 0; p < 4; p++) {
            int row = row0 + p * 16;
            float4 q4 = *(const float4*)&q[(size_t)(b * T_SZ + qt * 64 + row) * C_SZ + h * HD + c4];
            q4.x *= 0.125f; q4.y *= 0.125f; q4.z *= 0.125f; q4.w *= 0.125f;
            *(float4*)&Qs[row][c4] = q4;
        }
    }

    float m = -INFINITY;
    float l = 0.0f;
    float acc[16];
#pragma unroll
    for (int i = 0; i < 16; i++) acc[i] = 0.0f;

    for (int kt = 0; kt <= qt; kt++) {
        __syncthreads();   // prior iter's Vs/Ps reads done; Q visible on first iter
        // load K, V tiles
        {
            int c4 = (tid & 15) * 4;
            int row0 = tid >> 4;
#pragma unroll
            for (int p = 0; p < 4; p++) {
                int row = row0 + p * 16;
                size_t base = (size_t)(b * T_SZ + kt * 64 + row) * KVDIM + hk * HD + c4;
                *(float4*)&Ks[row][c4] = *(const float4*)&k[base];
                *(float4*)&Vs[row][c4] = *(const float4*)&v[base];
            }
        }
        __syncthreads();

        // S = Q K^T for 16 columns j = quad + 4*jj
        float s[16];
#pragma unroll
        for (int jj = 0; jj < 16; jj++) s[jj] = 0.0f;
#pragma unroll 4
        for (int d4 = 0; d4 < 16; d4++) {
            float4 q4 = *(float4*)&Qs[r][d4 * 4];
#pragma unroll
            for (int jj = 0; jj < 16; jj++) {
                int j = quad + 4 * jj;
                float4 k4 = *(float4*)&Ks[j][d4 * 4];
                s[jj] += q4.x * k4.x + q4.y * k4.y + q4.z * k4.z + q4.w * k4.w;
            }
        }

        // causal mask (diagonal tile only)
        if (kt == qt) {
#pragma unroll
            for (int jj = 0; jj < 16; jj++)
                if (quad + 4 * jj > r) s[jj] = -INFINITY;
        }

        // online softmax
        float mt = -INFINITY;
#pragma unroll
        for (int jj = 0; jj < 16; jj++) mt = fmaxf(mt, s[jj]);
        mt = fmaxf(mt, __shfl_xor_sync(0xffffffffu, mt, 1));
        mt = fmaxf(mt, __shfl_xor_sync(0xffffffffu, mt, 2));
        float mnew = fmaxf(m, mt);
        float alpha = expf(m - mnew);   // 0 on first tile (m=-inf)

        float lloc = 0.0f;
#pragma unroll
        for (int jj = 0; jj < 16; jj++) {
            float p = expf(s[jj] - mnew);
            lloc += p;
            Ps[r][quad + 4 * jj] = p;
        }
        lloc += __shfl_xor_sync(0xffffffffu, lloc, 1);
        lloc += __shfl_xor_sync(0xffffffffu, lloc, 2);
        l = l * alpha + lloc;
        m = mnew;
#pragma unroll
        for (int i = 0; i < 16; i++) acc[i] *= alpha;

        __syncthreads();   // Ps visible

        // acc += P @ V on dims d0..d0+15
        int d0 = quad * 16;
#pragma unroll 4
        for (int j = 0; j < 64; j++) {
            float pv = Ps[r][j];
#pragma unroll
            for (int dd4 = 0; dd4 < 4; dd4++) {
                float4 v4 = *(float4*)&Vs[j][d0 + dd4 * 4];
                acc[dd4 * 4 + 0] += pv * v4.x;
                acc[dd4 * 4 + 1] += pv * v4.y;
                acc[dd4 * 4 + 2] += pv * v4.z;
                acc[dd4 * 4 + 3] += pv * v4.w;
            }
        }
    }

    // normalize + store
    float inv = 1.0f / l;
    int grow = b * T_SZ + qt * 64 + r;
    int d0 = quad * 16;
#pragma unroll
    for (int dd4 = 0; dd4 < 4; dd4++) {
        float4 o = make_float4(acc[dd4 * 4 + 0] * inv, acc[dd4 * 4 + 1] * inv,
                               acc[dd4 * 4 + 2] * inv, acc[dd4 * 4 + 3] * inv);
        *(float4*)&y[(size_t)grow * C_SZ + h * HD + d0 + dd4 * 4] = o;
    }
}

// ---------------------------------------------------------------------------
extern "C" void kernel_launch(void* const* d_in, const int* in_sizes, int n_in,
                              void* d_out, int out_size) {
    const float* x  = (const float*)d_in[0];
    const float* Wq = (const float*)d_in[1];
    const float* Wk = (const float*)d_in[2];
    const float* Wv = (const float*)d_in[3];
    const float* Wo = (const float*)d_in[4];
    float* out = (float*)d_out;

    float *pq, *pk, *pv, *py;
    cudaGetSymbolAddress((void**)&pq, g_q);
    cudaGetSymbolAddress((void**)&pk, g_k);
    cudaGetSymbolAddress((void**)&pv, g_v);
    cudaGetSymbolAddress((void**)&py, g_y);

    // projections
    gemm_kernel<<<dim3(C_SZ / GBN, ROWS / GBM), 256>>>(x, Wq, pq, ROWS, C_SZ, C_SZ);
    gemm_kernel<<<dim3(KVDIM / GBN, ROWS / GBM), 256>>>(x, Wk, pk, ROWS, KVDIM, C_SZ);
    gemm_kernel<<<dim3(KVDIM / GBN, ROWS / GBM), 256>>>(x, Wv, pv, ROWS, KVDIM, C_SZ);

    // RoPE
    {
        int tq = ROWS * NH * 32;
        rope_kernel<<<(tq + 255) / 256, 256>>>(pq, NH);
        int tk = ROWS * NKV * 32;
        rope_kernel<<<(tk + 255) / 256, 256>>>(pk, NKV);
    }

    // flash attention
    {
        int smem = 4 * 64 * FPAD * (int)sizeof(float);   // 69632 B
        cudaFuncSetAttribute(flash_kernel, cudaFuncAttributeMaxDynamicSharedMemorySize, smem);
        flash_kernel<<<dim3(T_SZ / 64, NH, B_SZ), 256, smem>>>(pq, pk, pv, py);
    }

    // output projection
    gemm_kernel<<<dim3(C_SZ / GBN, ROWS / GBM), 256>>>(py, Wo, out, ROWS, C_SZ, C_SZ);
}

// round 3
// speedup vs baseline: 2.2001x; 2.2001x over previous
#include <cuda_runtime.h>
#include <cuda_bf16.h>
#include <math.h>

// Problem constants
#define B_SZ 2
#define T_SZ 2048
#define C_SZ 2048
#define NH 32
#define NKV 8
#define HD 64
#define ROWS (B_SZ * T_SZ)          // 4096
#define KVDIM (NKV * HD)            // 512

typedef __nv_bfloat16 bf16;

// Scratch (allocation-free: __device__ globals)
__device__ float g_q[ROWS * C_SZ];
__device__ float g_k[ROWS * KVDIM];
__device__ float g_v[ROWS * KVDIM];
__device__ float g_y[ROWS * C_SZ];

// bf16 hi/lo planes
__device__ bf16 g_xh[ROWS * C_SZ], g_xl[ROWS * C_SZ];
__device__ bf16 g_yh[ROWS * C_SZ], g_yl[ROWS * C_SZ];
__device__ bf16 g_wqh[C_SZ * C_SZ], g_wql[C_SZ * C_SZ];        // Wq^T [N][K]
__device__ bf16 g_wkh[KVDIM * C_SZ], g_wkl[KVDIM * C_SZ];      // Wk^T
__device__ bf16 g_wvh[KVDIM * C_SZ], g_wvl[KVDIM * C_SZ];      // Wv^T
__device__ bf16 g_woh[C_SZ * C_SZ], g_wol[C_SZ * C_SZ];        // Wo^T

// ---------------------------------------------------------------------------
// Elementwise fp32 -> bf16 hi/lo split
// ---------------------------------------------------------------------------
__global__ void split_kernel(const float* __restrict__ x, bf16* __restrict__ hi,
                             bf16* __restrict__ lo, int n) {
    int i = blockIdx.x * blockDim.x + threadIdx.x;
    if (i >= n) return;
    float v = x[i];
    bf16 h = __float2bfloat16(v);
    hi[i] = h;
    lo[i] = __float2bfloat16(v - __bfloat162float(h));
}

// ---------------------------------------------------------------------------
// Transpose + split: W [K][N] fp32 -> hi/lo [N][K] bf16
// ---------------------------------------------------------------------------
__global__ void tsplit_kernel(const float* __restrict__ W, bf16* __restrict__ hi,
                              bf16* __restrict__ lo, int K, int N) {
    __shared__ float s[32][33];
    int tx = threadIdx.x, ty = threadIdx.y;     // 32 x 8
    int gn = blockIdx.x * 32, gk = blockIdx.y * 32;
#pragma unroll
    for (int j = 0; j < 4; j++)
        s[ty + j * 8][tx] = W[(size_t)(gk + ty + j * 8) * N + gn + tx];
    __syncthreads();
#pragma unroll
    for (int j = 0; j < 4; j++) {
        float v = s[tx][ty + j * 8];
        bf16 h = __float2bfloat16(v);
        size_t o = (size_t)(gn + ty + j * 8) * K + gk + tx;
        hi[o] = h;
        lo[o] = __float2bfloat16(v - __bfloat162float(h));
    }
}

// ---------------------------------------------------------------------------
// bf16x3 tensor-core GEMM: C[M,N] = A[M,K] @ Bt[N,K]^T, fp32-comparable accuracy.
// A given as hi/lo bf16 planes [M][K]; B as transposed hi/lo planes [N][K].
// Block 128x128x32, 256 threads, warp tile 64x32, mma.m16n8k16.bf16,
// 3 MMAs (hh, hl, lh) per tile. cp.async double buffered.
// ---------------------------------------------------------------------------
#define BM 128
#define BN 128
#define BK 32
#define KSTR 40                 // smem row stride in bf16 (conflict-free u32 LDS)
#define PLANE (128 * KSTR)      // bf16 elems per plane (5120)
#define PLANE32 (PLANE / 2)     // u32 elems per plane (2560)

#define CP_ASYNC16(dst, src) \
    asm volatile("cp.async.cg.shared.global [%0], [%1], 16;\n" :: "r"(dst), "l"(src))

#define MMA_BF16(d, a, b) \
    asm volatile("mma.sync.aligned.m16n8k16.row.col.f32.bf16.bf16.f32 " \
                 "{%0,%1,%2,%3}, {%4,%5,%6,%7}, {%8,%9}, {%0,%1,%2,%3};\n" \
                 : "+f"(d[0]), "+f"(d[1]), "+f"(d[2]), "+f"(d[3]) \
                 : "r"(a[0]), "r"(a[1]), "r"(a[2]), "r"(a[3]), "r"(b[0]), "r"(b[1]))

__global__ __launch_bounds__(256) void gemm_b3(const bf16* __restrict__ Ah,
                                               const bf16* __restrict__ Al,
                                               const bf16* __restrict__ Bh,
                                               const bf16* __restrict__ Bl,
                                               float* __restrict__ C,
                                               int M, int N, int K) {
    extern __shared__ bf16 sm[];

    int tid = threadIdx.x;
    int warp = tid >> 5, lane = tid & 31;
    int g = lane >> 2, tg = lane & 3;
    int wm = (warp & 1) * 64;
    int wn = (warp >> 1) * 32;
    int brow = blockIdx.y * BM, bcol = blockIdx.x * BN;

    float acc[4][4][4] = {};
    const int nK = K / BK;

    auto loadTile = [&](int kt, int buf) {
        bf16* dstb = sm + buf * (4 * PLANE);
#pragma unroll
        for (int i = 0; i < 8; i++) {
            int idx = tid + i * 256;
            int plane = idx >> 9;          // constant per unrolled i
            int rem = idx & 511;
            int row = rem >> 2, c = rem & 3;
            const bf16* src;
            if (plane == 0)      src = Ah + (size_t)(brow + row) * K;
            else if (plane == 1) src = Al + (size_t)(brow + row) * K;
            else if (plane == 2) src = Bh + (size_t)(bcol + row) * K;
            else                 src = Bl + (size_t)(bcol + row) * K;
            src += kt * BK + c * 8;
            unsigned d = (unsigned)__cvta_generic_to_shared(dstb + plane * PLANE + row * KSTR + c * 8);
            CP_ASYNC16(d, src);
        }
        asm volatile("cp.async.commit_group;\n");
    };

    loadTile(0, 0);

    for (int kt = 0; kt < nK; kt++) {
        if (kt + 1 < nK) {
            loadTile(kt + 1, (kt + 1) & 1);
            asm volatile("cp.async.wait_group 1;\n");
        } else {
            asm volatile("cp.async.wait_group 0;\n");
        }
        __syncthreads();

        const unsigned* ah = (const unsigned*)(sm + (kt & 1) * (4 * PLANE));
        const unsigned* al = ah + PLANE32;
        const unsigned* bh = ah + 2 * PLANE32;
        const unsigned* bl = ah + 3 * PLANE32;

#pragma unroll
        for (int ks = 0; ks < 2; ks++) {
            int kc = ks * 8 + tg;                 // u32 column
            unsigned Afh[4][4], Afl[4][4], Bfh[4][2], Bfl[4][2];
#pragma unroll
            for (int mt = 0; mt < 4; mt++) {
                int o = (wm + mt * 16 + g) * 20 + kc;
                Afh[mt][0] = ah[o];       Afh[mt][1] = ah[o + 160];
                Afh[mt][2] = ah[o + 4];   Afh[mt][3] = ah[o + 164];
                Afl[mt][0] = al[o];       Afl[mt][1] = al[o + 160];
                Afl[mt][2] = al[o + 4];   Afl[mt][3] = al[o + 164];
            }
#pragma unroll
            for (int nt = 0; nt < 4; nt++) {
                int o = (wn + nt * 8 + g) * 20 + kc;
                Bfh[nt][0] = bh[o];  Bfh[nt][1] = bh[o + 4];
                Bfl[nt][0] = bl[o];  Bfl[nt][1] = bl[o + 4];
            }
#pragma unroll
            for (int mt = 0; mt < 4; mt++)
#pragma unroll
                for (int nt = 0; nt < 4; nt++) {
                    MMA_BF16(acc[mt][nt], Afh[mt], Bfh[nt]);
                    MMA_BF16(acc[mt][nt], Afh[mt], Bfl[nt]);
                    MMA_BF16(acc[mt][nt], Afl[mt], Bfh[nt]);
                }
        }
        __syncthreads();
    }

    // epilogue: c0,c1 -> (row g, cols 2tg,2tg+1); c2,c3 -> row g+8
#pragma unroll
    for (int mt = 0; mt < 4; mt++) {
        int r0 = brow + wm + mt * 16 + g;
#pragma unroll
        for (int nt = 0; nt < 4; nt++) {
            int c0 = bcol + wn + nt * 8 + tg * 2;
            *(float2*)&C[(size_t)r0 * N + c0] = make_float2(acc[mt][nt][0], acc[mt][nt][1]);
            *(float2*)&C[(size_t)(r0 + 8) * N + c0] = make_float2(acc[mt][nt][2], acc[mt][nt][3]);
        }
    }
}

// ---------------------------------------------------------------------------
// RoPE in-place on [ROWS, nheads*64]
// ---------------------------------------------------------------------------
__global__ void rope_kernel(float* __restrict__ x, int nheads) {
    int idx = blockIdx.x * blockDim.x + threadIdx.x;
    int total = ROWS * nheads * 32;
    if (idx >= total) return;
    int i = idx & 31;
    int h = (idx >> 5) % nheads;
    int row = idx / (32 * nheads);
    int t = row & (T_SZ - 1);

    float invf = expf(-(float)i * 0.28782313662425574f);  // ln(10000)/32
    float ang = (float)t * invf;
    float c = cosf(ang), s = sinf(ang);

    float* p = x + (size_t)row * (nheads * HD) + h * HD;
    float x0 = p[i];
    float x1 = p[i + 32];
    p[i]      = x0 * c - x1 * s;
    p[i + 32] = x1 * c + x0 * s;
}

// ---------------------------------------------------------------------------
// Flash attention (causal, fp32) — unchanged from R1 (passing baseline).
// ---------------------------------------------------------------------------
#define FPAD 68
__global__ __launch_bounds__(256) void flash_kernel(const float* __restrict__ q,
                                                    const float* __restrict__ k,
                                                    const float* __restrict__ v,
                                                    float* __restrict__ y) {
    extern __shared__ float smf[];
    float (*Qs)[FPAD] = (float(*)[FPAD])smf;
    float (*Ks)[FPAD] = (float(*)[FPAD])(smf + 64 * FPAD);
    float (*Vs)[FPAD] = (float(*)[FPAD])(smf + 2 * 64 * FPAD);
    float (*Ps)[FPAD] = (float(*)[FPAD])(smf + 3 * 64 * FPAD);

    int qt = blockIdx.x;
    int h  = blockIdx.y;
    int b  = blockIdx.z;
    int hk = h >> 2;

    int tid = threadIdx.x;
    int r = tid >> 2;
    int quad = tid & 3;

    {
        int c4 = (tid & 15) * 4;
        int row0 = tid >> 4;
#pragma unroll
        for (int p = 0; p < 4; p++) {
            int row = row0 + p * 16;
            float4 q4 = *(const float4*)&q[(size_t)(b * T_SZ + qt * 64 + row) * C_SZ + h * HD + c4];
            q4.x *= 0.125f; q4.y *= 0.125f; q4.z *= 0.125f; q4.w *= 0.125f;
            *(float4*)&Qs[row][c4] = q4;
        }
    }

    float m = -INFINITY;
    float l = 0.0f;
    float acc[16];
#pragma unroll
    for (int i = 0; i < 16; i++) acc[i] = 0.0f;

    for (int kt = 0; kt <= qt; kt++) {
        __syncthreads();
        {
            int c4 = (tid & 15) * 4;
            int row0 = tid >> 4;
#pragma unroll
            for (int p = 0; p < 4; p++) {
                int row = row0 + p * 16;
                size_t base = (size_t)(b * T_SZ + kt * 64 + row) * KVDIM + hk * HD + c4;
                *(float4*)&Ks[row][c4] = *(const float4*)&k[base];
                *(float4*)&Vs[row][c4] = *(const float4*)&v[base];
            }
        }
        __syncthreads();

        float s[16];
#pragma unroll
        for (int jj = 0; jj < 16; jj++) s[jj] = 0.0f;
#pragma unroll 4
        for (int d4 = 0; d4 < 16; d4++) {
            float4 q4 = *(float4*)&Qs[r][d4 * 4];
#pragma unroll
            for (int jj = 0; jj < 16; jj++) {
                int j = quad + 4 * jj;
                float4 k4 = *(float4*)&Ks[j][d4 * 4];
                s[jj] += q4.x * k4.x + q4.y * k4.y + q4.z * k4.z + q4.w * k4.w;
            }
        }

        if (kt == qt) {
#pragma unroll
            for (int jj = 0; jj < 16; jj++)
                if (quad + 4 * jj > r) s[jj] = -INFINITY;
        }

        float mt = -INFINITY;
#pragma unroll
        for (int jj = 0; jj < 16; jj++) mt = fmaxf(mt, s[jj]);
        mt = fmaxf(mt, __shfl_xor_sync(0xffffffffu, mt, 1));
        mt = fmaxf(mt, __shfl_xor_sync(0xffffffffu, mt, 2));
        float mnew = fmaxf(m, mt);
        float alpha = expf(m - mnew);

        float lloc = 0.0f;
#pragma unroll
        for (int jj = 0; jj < 16; jj++) {
            float p = expf(s[jj] - mnew);
            lloc += p;
            Ps[r][quad + 4 * jj] = p;
        }
        lloc += __shfl_xor_sync(0xffffffffu, lloc, 1);
        lloc += __shfl_xor_sync(0xffffffffu, lloc, 2);
        l = l * alpha + lloc;
        m = mnew;
#pragma unroll
        for (int i = 0; i < 16; i++) acc[i] *= alpha;

        __syncthreads();

        int d0 = quad * 16;
#pragma unroll 4
        for (int j = 0; j < 64; j++) {
            float pv = Ps[r][j];
#pragma unroll
            for (int dd4 = 0; dd4 < 4; dd4++) {
                float4 v4 = *(float4*)&Vs[j][d0 + dd4 * 4];
                acc[dd4 * 4 + 0] += pv * v4.x;
                acc[dd4 * 4 + 1] += pv * v4.y;
                acc[dd4 * 4 + 2] += pv * v4.z;
                acc[dd4 * 4 + 3] += pv * v4.w;
            }
        }
    }

    float inv = 1.0f / l;
    int grow = b * T_SZ + qt * 64 + r;
    int d0 = quad * 16;
#pragma unroll
    for (int dd4 = 0; dd4 < 4; dd4++) {
        float4 o = make_float4(acc[dd4 * 4 + 0] * inv, acc[dd4 * 4 + 1] * inv,
                               acc[dd4 * 4 + 2] * inv, acc[dd4 * 4 + 3] * inv);
        *(float4*)&y[(size_t)grow * C_SZ + h * HD + d0 + dd4 * 4] = o;
    }
}

// ---------------------------------------------------------------------------
extern "C" void kernel_launch(void* const* d_in, const int* in_sizes, int n_in,
                              void* d_out, int out_size) {
    const float* x  = (const float*)d_in[0];
    const float* Wq = (const float*)d_in[1];
    const float* Wk = (const float*)d_in[2];
    const float* Wv = (const float*)d_in[3];
    const float* Wo = (const float*)d_in[4];
    float* out = (float*)d_out;

    float *pq, *pk, *pv, *py;
    cudaGetSymbolAddress((void**)&pq, g_q);
    cudaGetSymbolAddress((void**)&pk, g_k);
    cudaGetSymbolAddress((void**)&pv, g_v);
    cudaGetSymbolAddress((void**)&py, g_y);

    bf16 *xh, *xl, *yh, *yl, *wqh, *wql, *wkh, *wkl, *wvh, *wvl, *woh, *wol;
    cudaGetSymbolAddress((void**)&xh, g_xh);  cudaGetSymbolAddress((void**)&xl, g_xl);
    cudaGetSymbolAddress((void**)&yh, g_yh);  cudaGetSymbolAddress((void**)&yl, g_yl);
    cudaGetSymbolAddress((void**)&wqh, g_wqh); cudaGetSymbolAddress((void**)&wql, g_wql);
    cudaGetSymbolAddress((void**)&wkh, g_wkh); cudaGetSymbolAddress((void**)&wkl, g_wkl);
    cudaGetSymbolAddress((void**)&wvh, g_wvh); cudaGetSymbolAddress((void**)&wvl, g_wvl);
    cudaGetSymbolAddress((void**)&woh, g_woh); cudaGetSymbolAddress((void**)&wol, g_wol);

    int gemm_smem = 2 * 4 * PLANE * (int)sizeof(bf16);   // 81920
    cudaFuncSetAttribute(gemm_b3, cudaFuncAttributeMaxDynamicSharedMemorySize, gemm_smem);
    int fsmem = 4 * 64 * FPAD * (int)sizeof(float);      // 69632
    cudaFuncSetAttribute(flash_kernel, cudaFuncAttributeMaxDynamicSharedMemorySize, fsmem);

    // split inputs / weights
    {
        int n = ROWS * C_SZ;
        split_kernel<<<(n + 255) / 256, 256>>>(x, xh, xl, n);
        tsplit_kernel<<<dim3(C_SZ / 32, C_SZ / 32), dim3(32, 8)>>>(Wq, wqh, wql, C_SZ, C_SZ);
        tsplit_kernel<<<dim3(KVDIM / 32, C_SZ / 32), dim3(32, 8)>>>(Wk, wkh, wkl, C_SZ, KVDIM);
        tsplit_kernel<<<dim3(KVDIM / 32, C_SZ / 32), dim3(32, 8)>>>(Wv, wvh, wvl, C_SZ, KVDIM);
        tsplit_kernel<<<dim3(C_SZ / 32, C_SZ / 32), dim3(32, 8)>>>(Wo, woh, wol, C_SZ, C_SZ);
    }

    // projections (bf16x3 tensor cores)
    gemm_b3<<<dim3(C_SZ / BN, ROWS / BM), 256, gemm_smem>>>(xh, xl, wqh, wql, pq, ROWS, C_SZ, C_SZ);
    gemm_b3<<<dim3(KVDIM / BN, ROWS / BM), 256, gemm_smem>>>(xh, xl, wkh, wkl, pk, ROWS, KVDIM, C_SZ);
    gemm_b3<<<dim3(KVDIM / BN, ROWS / BM), 256, gemm_smem>>>(xh, xl, wvh, wvl, pv, ROWS, KVDIM, C_SZ);

    // RoPE
    {
        int tq = ROWS * NH * 32;
        rope_kernel<<<(tq + 255) / 256, 256>>>(pq, NH);
        int tk = ROWS * NKV * 32;
        rope_kernel<<<(tk + 255) / 256, 256>>>(pk, NKV);
    }

    // flash attention (fp32)
    flash_kernel<<<dim3(T_SZ / 64, NH, B_SZ), 256, fsmem>>>(pq, pk, pv, py);

    // output projection
    {
        int n = ROWS * C_SZ;
        split_kernel<<<(n + 255) / 256, 256>>>(py, yh, yl, n);
        gemm_b3<<<dim3(C_SZ / BN, ROWS / BM), 256, gemm_smem>>>(yh, yl, woh, wol, out, ROWS, C_SZ, C_SZ);
    }
}

// round 4
// speedup vs baseline: 7.5505x; 3.4318x over previous
#include <cuda_runtime.h>
#include <cuda_bf16.h>
#include <math.h>

// Problem constants
#define B_SZ 2
#define T_SZ 2048
#define C_SZ 2048
#define NH 32
#define NKV 8
#define HD 64
#define ROWS (B_SZ * T_SZ)          // 4096
#define KVDIM (NKV * HD)            // 512

typedef __nv_bfloat16 bf16;

// Scratch (allocation-free: __device__ globals)
__device__ float g_q[ROWS * C_SZ];
__device__ float g_k[ROWS * KVDIM];
__device__ float g_v[ROWS * KVDIM];
__device__ float g_y[ROWS * C_SZ];

// bf16 hi/lo planes
__device__ bf16 g_xh[ROWS * C_SZ], g_xl[ROWS * C_SZ];
__device__ bf16 g_yh[ROWS * C_SZ], g_yl[ROWS * C_SZ];
__device__ bf16 g_wqh[C_SZ * C_SZ], g_wql[C_SZ * C_SZ];        // Wq^T [N][K]
__device__ bf16 g_wkh[KVDIM * C_SZ], g_wkl[KVDIM * C_SZ];      // Wk^T
__device__ bf16 g_wvh[KVDIM * C_SZ], g_wvl[KVDIM * C_SZ];      // Wv^T
__device__ bf16 g_woh[C_SZ * C_SZ], g_wol[C_SZ * C_SZ];        // Wo^T

#define CP_ASYNC16(dst, src) \
    asm volatile("cp.async.cg.shared.global [%0], [%1], 16;\n" :: "r"(dst), "l"(src))

__device__ __forceinline__ unsigned cvt_tf32(float f) {
    unsigned u;
    asm("cvt.rna.tf32.f32 %0, %1;" : "=r"(u) : "f"(f));
    return u;
}

#define MMA_TF32(d, a, b) \
    asm volatile("mma.sync.aligned.m16n8k8.row.col.f32.tf32.tf32.f32 " \
                 "{%0,%1,%2,%3}, {%4,%5,%6,%7}, {%8,%9}, {%0,%1,%2,%3};\n" \
                 : "+f"(d[0]), "+f"(d[1]), "+f"(d[2]), "+f"(d[3]) \
                 : "r"(a[0]), "r"(a[1]), "r"(a[2]), "r"(a[3]), "r"(b[0]), "r"(b[1]))

#define MMA_BF16(d, a, b) \
    asm volatile("mma.sync.aligned.m16n8k16.row.col.f32.bf16.bf16.f32 " \
                 "{%0,%1,%2,%3}, {%4,%5,%6,%7}, {%8,%9}, {%0,%1,%2,%3};\n" \
                 : "+f"(d[0]), "+f"(d[1]), "+f"(d[2]), "+f"(d[3]) \
                 : "r"(a[0]), "r"(a[1]), "r"(a[2]), "r"(a[3]), "r"(b[0]), "r"(b[1]))

// ---------------------------------------------------------------------------
// Elementwise fp32 -> bf16 hi/lo split
// ---------------------------------------------------------------------------
__global__ void split_kernel(const float* __restrict__ x, bf16* __restrict__ hi,
                             bf16* __restrict__ lo, int n) {
    int i = blockIdx.x * blockDim.x + threadIdx.x;
    if (i >= n) return;
    float v = x[i];
    bf16 h = __float2bfloat16(v);
    hi[i] = h;
    lo[i] = __float2bfloat16(v - __bfloat162float(h));
}

// ---------------------------------------------------------------------------
// Transpose + split: W [K][N] fp32 -> hi/lo [N][K] bf16
// ---------------------------------------------------------------------------
__global__ void tsplit_kernel(const float* __restrict__ W, bf16* __restrict__ hi,
                              bf16* __restrict__ lo, int K, int N) {
    __shared__ float s[32][33];
    int tx = threadIdx.x, ty = threadIdx.y;     // 32 x 8
    int gn = blockIdx.x * 32, gk = blockIdx.y * 32;
#pragma unroll
    for (int j = 0; j < 4; j++)
        s[ty + j * 8][tx] = W[(size_t)(gk + ty + j * 8) * N + gn + tx];
    __syncthreads();
#pragma unroll
    for (int j = 0; j < 4; j++) {
        float v = s[tx][ty + j * 8];
        bf16 h = __float2bfloat16(v);
        size_t o = (size_t)(gn + ty + j * 8) * K + gk + tx;
        hi[o] = h;
        lo[o] = __float2bfloat16(v - __bfloat162float(h));
    }
}

// ---------------------------------------------------------------------------
// bf16x3 tensor-core GEMM (unchanged from R3, passing)
// ---------------------------------------------------------------------------
#define BM 128
#define BN 128
#define BK 32
#define KSTR 40
#define PLANE (128 * KSTR)
#define PLANE32 (PLANE / 2)

__global__ __launch_bounds__(256) void gemm_b3(const bf16* __restrict__ Ah,
                                               const bf16* __restrict__ Al,
                                               const bf16* __restrict__ Bh,
                                               const bf16* __restrict__ Bl,
                                               float* __restrict__ C,
                                               int M, int N, int K) {
    extern __shared__ bf16 sm[];

    int tid = threadIdx.x;
    int warp = tid >> 5, lane = tid & 31;
    int g = lane >> 2, tg = lane & 3;
    int wm = (warp & 1) * 64;
    int wn = (warp >> 1) * 32;
    int brow = blockIdx.y * BM, bcol = blockIdx.x * BN;

    float acc[4][4][4] = {};
    const int nK = K / BK;

    auto loadTile = [&](int kt, int buf) {
        bf16* dstb = sm + buf * (4 * PLANE);
#pragma unroll
        for (int i = 0; i < 8; i++) {
            int idx = tid + i * 256;
            int plane = idx >> 9;
            int rem = idx & 511;
            int row = rem >> 2, c = rem & 3;
            const bf16* src;
            if (plane == 0)      src = Ah + (size_t)(brow + row) * K;
            else if (plane == 1) src = Al + (size_t)(brow + row) * K;
            else if (plane == 2) src = Bh + (size_t)(bcol + row) * K;
            else                 src = Bl + (size_t)(bcol + row) * K;
            src += kt * BK + c * 8;
            unsigned d = (unsigned)__cvta_generic_to_shared(dstb + plane * PLANE + row * KSTR + c * 8);
            CP_ASYNC16(d, src);
        }
        asm volatile("cp.async.commit_group;\n");
    };

    loadTile(0, 0);

    for (int kt = 0; kt < nK; kt++) {
        if (kt + 1 < nK) {
            loadTile(kt + 1, (kt + 1) & 1);
            asm volatile("cp.async.wait_group 1;\n");
        } else {
            asm volatile("cp.async.wait_group 0;\n");
        }
        __syncthreads();

        const unsigned* ah = (const unsigned*)(sm + (kt & 1) * (4 * PLANE));
        const unsigned* al = ah + PLANE32;
        const unsigned* bh = ah + 2 * PLANE32;
        const unsigned* bl = ah + 3 * PLANE32;

#pragma unroll
        for (int ks = 0; ks < 2; ks++) {
            int kc = ks * 8 + tg;
            unsigned Afh[4][4], Afl[4][4], Bfh[4][2], Bfl[4][2];
#pragma unroll
            for (int mt = 0; mt < 4; mt++) {
                int o = (wm + mt * 16 + g) * 20 + kc;
                Afh[mt][0] = ah[o];       Afh[mt][1] = ah[o + 160];
                Afh[mt][2] = ah[o + 4];   Afh[mt][3] = ah[o + 164];
                Afl[mt][0] = al[o];       Afl[mt][1] = al[o + 160];
                Afl[mt][2] = al[o + 4];   Afl[mt][3] = al[o + 164];
            }
#pragma unroll
            for (int nt = 0; nt < 4; nt++) {
                int o = (wn + nt * 8 + g) * 20 + kc;
                Bfh[nt][0] = bh[o];  Bfh[nt][1] = bh[o + 4];
                Bfl[nt][0] = bl[o];  Bfl[nt][1] = bl[o + 4];
            }
#pragma unroll
            for (int mt = 0; mt < 4; mt++)
#pragma unroll
                for (int nt = 0; nt < 4; nt++) {
                    MMA_BF16(acc[mt][nt], Afh[mt], Bfh[nt]);
                    MMA_BF16(acc[mt][nt], Afh[mt], Bfl[nt]);
                    MMA_BF16(acc[mt][nt], Afl[mt], Bfh[nt]);
                }
        }
        __syncthreads();
    }

#pragma unroll
    for (int mt = 0; mt < 4; mt++) {
        int r0 = brow + wm + mt * 16 + g;
#pragma unroll
        for (int nt = 0; nt < 4; nt++) {
            int c0 = bcol + wn + nt * 8 + tg * 2;
            *(float2*)&C[(size_t)r0 * N + c0] = make_float2(acc[mt][nt][0], acc[mt][nt][1]);
            *(float2*)&C[(size_t)(r0 + 8) * N + c0] = make_float2(acc[mt][nt][2], acc[mt][nt][3]);
        }
    }
}

// ---------------------------------------------------------------------------
// RoPE in-place on [ROWS, nheads*64]
// ---------------------------------------------------------------------------
__global__ void rope_kernel(float* __restrict__ x, int nheads) {
    int idx = blockIdx.x * blockDim.x + threadIdx.x;
    int total = ROWS * nheads * 32;
    if (idx >= total) return;
    int i = idx & 31;
    int h = (idx >> 5) % nheads;
    int row = idx / (32 * nheads);
    int t = row & (T_SZ - 1);

    float invf = expf(-(float)i * 0.28782313662425574f);  // ln(10000)/32
    float ang = (float)t * invf;
    float c = cosf(ang), s = sinf(ang);

    float* p = x + (size_t)row * (nheads * HD) + h * HD;
    float x0 = p[i];
    float x1 = p[i + 32];
    p[i]      = x0 * c - x1 * s;
    p[i + 32] = x1 * c + x0 * s;
}

// ---------------------------------------------------------------------------
// TF32 tensor-core flash attention (causal).
// Block: 128 q-rows x 1 head x 1 batch. 8 warps, each 16 S-rows.
// K/V tiles of 64 keys, fp32 in smem (stride 68), double-buffered cp.async.
// Q fragments in registers (tf32 rna, pre-scaled). S and PV via m16n8k8 tf32.
// PV uses k-permutation invariance: A pos tg <- P col 2tg, pos tg+4 <- 2tg+1,
// matched by B rows V[2tg], V[2tg+1].
// ---------------------------------------------------------------------------
#define FQ 128
#define FK 64
#define FSTR 68
#define FBUF (FK * FSTR * 2)   // floats per buffer (K + V) = 8704

__global__ __launch_bounds__(256, 2) void flash_tc(const float* __restrict__ q,
                                                   const float* __restrict__ k,
                                                   const float* __restrict__ v,
                                                   float* __restrict__ y) {
    extern __shared__ float smf[];
    int qt = blockIdx.x, h = blockIdx.y, b = blockIdx.z;
    int hk = h >> 2;
    int tid = threadIdx.x, w = tid >> 5, lane = tid & 31;
    int g = lane >> 2, tg = lane & 3;
    int qbase = qt * FQ;
    size_t bT = (size_t)b * T_SZ;

    // stage Q tile (128x64) in smem (reuses buffer region)
    {
        const float* qg = q + (bT + qbase) * C_SZ + h * HD;
#pragma unroll
        for (int i = 0; i < 8; i++) {
            int idx = tid + i * 256;
            int r = idx >> 4, c4 = (idx & 15) * 4;
            unsigned d = (unsigned)__cvta_generic_to_shared(smf + r * FSTR + c4);
            CP_ASYNC16(d, qg + (size_t)r * C_SZ + c4);
        }
        asm volatile("cp.async.commit_group;\ncp.async.wait_group 0;\n");
    }
    __syncthreads();

    unsigned qa[8][4];
    {
        int r0 = w * 16 + g;
#pragma unroll
        for (int c = 0; c < 8; c++) {
            qa[c][0] = cvt_tf32(smf[r0 * FSTR + 8 * c + tg] * 0.125f);
            qa[c][1] = cvt_tf32(smf[(r0 + 8) * FSTR + 8 * c + tg] * 0.125f);
            qa[c][2] = cvt_tf32(smf[r0 * FSTR + 8 * c + tg + 4] * 0.125f);
            qa[c][3] = cvt_tf32(smf[(r0 + 8) * FSTR + 8 * c + tg + 4] * 0.125f);
        }
    }
    __syncthreads();

    auto loadKV = [&](int kt, int buf) {
        float* base = smf + buf * FBUF;
        const float* kg = k + (bT + kt * FK) * KVDIM + hk * HD;
        const float* vg = v + (bT + kt * FK) * KVDIM + hk * HD;
#pragma unroll
        for (int i = 0; i < 4; i++) {
            int idx = tid + i * 256;
            int r = idx >> 4, c4 = (idx & 15) * 4;
            unsigned dk = (unsigned)__cvta_generic_to_shared(base + r * FSTR + c4);
            CP_ASYNC16(dk, kg + (size_t)r * KVDIM + c4);
            unsigned dv = (unsigned)__cvta_generic_to_shared(base + FK * FSTR + r * FSTR + c4);
            CP_ASYNC16(dv, vg + (size_t)r * KVDIM + c4);
        }
        asm volatile("cp.async.commit_group;\n");
    };

    float yacc[8][4] = {};
    float m0 = -INFINITY, m1 = -INFINITY, l0 = 0.0f, l1 = 0.0f;
    int rg0 = qbase + w * 16 + g;

    int nkt = 2 * qt + 2;
    loadKV(0, 0);

    for (int kt = 0; kt < nkt; kt++) {
        if (kt + 1 < nkt) {
            loadKV(kt + 1, (kt + 1) & 1);
            asm volatile("cp.async.wait_group 1;\n");
        } else {
            asm volatile("cp.async.wait_group 0;\n");
        }
        __syncthreads();

        bool active = (FK * kt <= qbase + 16 * w + 15);
        if (active) {
            const float* Ks = smf + (kt & 1) * FBUF;
            const float* Vs = Ks + FK * FSTR;

            // S = Q K^T
            float sacc[8][4] = {};
#pragma unroll
            for (int c = 0; c < 8; c++) {
#pragma unroll
                for (int nf = 0; nf < 8; nf++) {
                    unsigned bb[2];
                    bb[0] = __float_as_uint(Ks[(8 * nf + g) * FSTR + 8 * c + tg]);
                    bb[1] = __float_as_uint(Ks[(8 * nf + g) * FSTR + 8 * c + tg + 4]);
                    MMA_TF32(sacc[nf], qa[c], bb);
                }
            }

            // causal mask on diagonal tiles
            if (kt >= 2 * qt) {
                int k0 = FK * kt;
#pragma unroll
                for (int nf = 0; nf < 8; nf++) {
                    int jg = k0 + 8 * nf + 2 * tg;
                    if (jg > rg0)     sacc[nf][0] = -INFINITY;
                    if (jg + 1 > rg0) sacc[nf][1] = -INFINITY;
                    if (jg > rg0 + 8)     sacc[nf][2] = -INFINITY;
                    if (jg + 1 > rg0 + 8) sacc[nf][3] = -INFINITY;
                }
            }

            // row max (two rows per thread)
            float mt0 = -INFINITY, mt1 = -INFINITY;
#pragma unroll
            for (int nf = 0; nf < 8; nf++) {
                mt0 = fmaxf(mt0, fmaxf(sacc[nf][0], sacc[nf][1]));
                mt1 = fmaxf(mt1, fmaxf(sacc[nf][2], sacc[nf][3]));
            }
            mt0 = fmaxf(mt0, __shfl_xor_sync(0xffffffffu, mt0, 1));
            mt0 = fmaxf(mt0, __shfl_xor_sync(0xffffffffu, mt0, 2));
            mt1 = fmaxf(mt1, __shfl_xor_sync(0xffffffffu, mt1, 1));
            mt1 = fmaxf(mt1, __shfl_xor_sync(0xffffffffu, mt1, 2));

            float mn0 = fmaxf(m0, mt0), mn1 = fmaxf(m1, mt1);
            float al0 = __expf(m0 - mn0), al1 = __expf(m1 - mn1);
            m0 = mn0; m1 = mn1;
#pragma unroll
            for (int nf = 0; nf < 8; nf++) {
                yacc[nf][0] *= al0; yacc[nf][1] *= al0;
                yacc[nf][2] *= al1; yacc[nf][3] *= al1;
            }

            // exp + PV (fused per k-chunk to bound register pressure)
            float pl0 = 0.0f, pl1 = 0.0f;
#pragma unroll
            for (int c = 0; c < 8; c++) {
                float p0 = __expf(sacc[c][0] - mn0);
                float p1 = __expf(sacc[c][1] - mn0);
                float p2 = __expf(sacc[c][2] - mn1);
                float p3 = __expf(sacc[c][3] - mn1);
                pl0 += p0 + p1;
                pl1 += p2 + p3;
                unsigned pa[4];
                pa[0] = cvt_tf32(p0);   // A pos tg    = P col 2tg   (row g)
                pa[1] = cvt_tf32(p2);   // row g+8
                pa[2] = cvt_tf32(p1);   // A pos tg+4  = P col 2tg+1 (row g)
                pa[3] = cvt_tf32(p3);   // row g+8
#pragma unroll
                for (int nf = 0; nf < 8; nf++) {
                    unsigned bb[2];
                    bb[0] = __float_as_uint(Vs[(8 * c + 2 * tg) * FSTR + 8 * nf + g]);
                    bb[1] = __float_as_uint(Vs[(8 * c + 2 * tg + 1) * FSTR + 8 * nf + g]);
                    MMA_TF32(yacc[nf], pa, bb);
                }
            }
            pl0 += __shfl_xor_sync(0xffffffffu, pl0, 1);
            pl0 += __shfl_xor_sync(0xffffffffu, pl0, 2);
            pl1 += __shfl_xor_sync(0xffffffffu, pl1, 1);
            pl1 += __shfl_xor_sync(0xffffffffu, pl1, 2);
            l0 = l0 * al0 + pl0;
            l1 = l1 * al1 + pl1;
        }
        __syncthreads();
    }

    // normalize + store
    float inv0 = 1.0f / l0, inv1 = 1.0f / l1;
    float* yo0 = y + (bT + qbase + w * 16 + g) * C_SZ + h * HD;
    float* yo1 = yo0 + 8 * C_SZ;
#pragma unroll
    for (int nf = 0; nf < 8; nf++) {
        *(float2*)&yo0[8 * nf + 2 * tg] = make_float2(yacc[nf][0] * inv0, yacc[nf][1] * inv0);
        *(float2*)&yo1[8 * nf + 2 * tg] = make_float2(yacc[nf][2] * inv1, yacc[nf][3] * inv1);
    }
}

// ---------------------------------------------------------------------------
extern "C" void kernel_launch(void* const* d_in, const int* in_sizes, int n_in,
                              void* d_out, int out_size) {
    const float* x  = (const float*)d_in[0];
    const float* Wq = (const float*)d_in[1];
    const float* Wk = (const float*)d_in[2];
    const float* Wv = (const float*)d_in[3];
    const float* Wo = (const float*)d_in[4];
    float* out = (float*)d_out;

    float *pq, *pk, *pv, *py;
    cudaGetSymbolAddress((void**)&pq, g_q);
    cudaGetSymbolAddress((void**)&pk, g_k);
    cudaGetSymbolAddress((void**)&pv, g_v);
    cudaGetSymbolAddress((void**)&py, g_y);

    bf16 *xh, *xl, *yh, *yl, *wqh, *wql, *wkh, *wkl, *wvh, *wvl, *woh, *wol;
    cudaGetSymbolAddress((void**)&xh, g_xh);  cudaGetSymbolAddress((void**)&xl, g_xl);
    cudaGetSymbolAddress((void**)&yh, g_yh);  cudaGetSymbolAddress((void**)&yl, g_yl);
    cudaGetSymbolAddress((void**)&wqh, g_wqh); cudaGetSymbolAddress((void**)&wql, g_wql);
    cudaGetSymbolAddress((void**)&wkh, g_wkh); cudaGetSymbolAddress((void**)&wkl, g_wkl);
    cudaGetSymbolAddress((void**)&wvh, g_wvh); cudaGetSymbolAddress((void**)&wvl, g_wvl);
    cudaGetSymbolAddress((void**)&woh, g_woh); cudaGetSymbolAddress((void**)&wol, g_wol);

    int gemm_smem = 2 * 4 * PLANE * (int)sizeof(bf16);   // 81920
    cudaFuncSetAttribute(gemm_b3, cudaFuncAttributeMaxDynamicSharedMemorySize, gemm_smem);
    int fsmem = 2 * FBUF * (int)sizeof(float);           // 69632
    cudaFuncSetAttribute(flash_tc, cudaFuncAttributeMaxDynamicSharedMemorySize, fsmem);

    // split inputs / weights
    {
        int n = ROWS * C_SZ;
        split_kernel<<<(n + 255) / 256, 256>>>(x, xh, xl, n);
        tsplit_kernel<<<dim3(C_SZ / 32, C_SZ / 32), dim3(32, 8)>>>(Wq, wqh, wql, C_SZ, C_SZ);
        tsplit_kernel<<<dim3(KVDIM / 32, C_SZ / 32), dim3(32, 8)>>>(Wk, wkh, wkl, C_SZ, KVDIM);
        tsplit_kernel<<<dim3(KVDIM / 32, C_SZ / 32), dim3(32, 8)>>>(Wv, wvh, wvl, C_SZ, KVDIM);
        tsplit_kernel<<<dim3(C_SZ / 32, C_SZ / 32), dim3(32, 8)>>>(Wo, woh, wol, C_SZ, C_SZ);
    }

    // projections (bf16x3 tensor cores)
    gemm_b3<<<dim3(C_SZ / BN, ROWS / BM), 256, gemm_smem>>>(xh, xl, wqh, wql, pq, ROWS, C_SZ, C_SZ);
    gemm_b3<<<dim3(KVDIM / BN, ROWS / BM), 256, gemm_smem>>>(xh, xl, wkh, wkl, pk, ROWS, KVDIM, C_SZ);
    gemm_b3<<<dim3(KVDIM / BN, ROWS / BM), 256, gemm_smem>>>(xh, xl, wvh, wvl, pv, ROWS, KVDIM, C_SZ);

    // RoPE
    {
        int tq = ROWS * NH * 32;
        rope_kernel<<<(tq + 255) / 256, 256>>>(pq, NH);
        int tk = ROWS * NKV * 32;
        rope_kernel<<<(tk + 255) / 256, 256>>>(pk, NKV);
    }

    // flash attention (tf32 tensor cores)
    flash_tc<<<dim3(T_SZ / FQ, NH, B_SZ), 256, fsmem>>>(pq, pk, pv, py);

    // output projection
    {
        int n = ROWS * C_SZ;
        split_kernel<<<(n + 255) / 256, 256>>>(py, yh, yl, n);
        gemm_b3<<<dim3(C_SZ / BN, ROWS / BM), 256, gemm_smem>>>(yh, yl, woh, wol, out, ROWS, C_SZ, C_SZ);
    }
}